// round 1
// baseline (speedup 1.0000x reference)
#include <cuda_runtime.h>
#include <math.h>

// Problem dims
#define B_  128
#define R_  1152
#define C_  10
#define O_  16
#define I_  338
#define N_  160               // C_*O_  (n = c*16 + o)
#define BRS (R_*N_)           // 184320 — per-batch stride in u_hat

// Scratch (device globals — allocation-free per harness rules)
__device__ float g_uhat[(size_t)B_ * R_ * N_];   // [b][r][n]  ~94.4 MB
__device__ float g_b[R_ * C_];                   // routing logits [r][c]
__device__ float g_c[R_ * C_];                   // softmax coeffs [r][c]
__device__ float g_v[B_ * N_];                   // v [b][n]

// ---------------------------------------------------------------------------
__global__ void zero_b_kernel() {
    int i = blockIdx.x * blockDim.x + threadIdx.x;
    if (i < R_ * C_) g_b[i] = 0.0f;
}

// ---------------------------------------------------------------------------
// u_hat[b][r][n] = sum_i W[r][n][i] * x[b][r][i]
// One block per route r. 256 threads, 8x10 register tile per thread
// (M=128 batch, N=160), K chunked by 32 into padded smem.
#define KC 32
__global__ __launch_bounds__(256) void uhat_kernel(const float* __restrict__ x,
                                                   const float* __restrict__ W) {
    const int r  = blockIdx.x;
    const int t  = threadIdx.x;
    const int tx = t & 15;        // N group
    const int ty = t >> 4;        // M group

    __shared__ float xs[KC][B_ + 1];   // [k][m], pad -> conflict-free
    __shared__ float ws[KC][N_ + 1];   // [k][n]

    const float* xr = x + (size_t)r * I_;          // + m*(R_*I_) per batch row
    const float* wr = W + (size_t)r * N_ * I_;     // 160 x 338 row-major

    float acc[8][10];
#pragma unroll
    for (int im = 0; im < 8; im++)
#pragma unroll
        for (int in = 0; in < 10; in++) acc[im][in] = 0.0f;

    for (int k0 = 0; k0 < I_; k0 += KC) {
        // load x tile: 128x32, coalesced gmem, strided (padded) smem store
        for (int e = t; e < B_ * KC; e += 256) {
            int m = e >> 5, kk = e & 31;
            int k = k0 + kk;
            xs[kk][m] = (k < I_) ? xr[(size_t)m * (R_ * I_) + k] : 0.0f;
        }
        // load W tile: 160x32
        for (int e = t; e < N_ * KC; e += 256) {
            int n = e >> 5, kk = e & 31;
            int k = k0 + kk;
            ws[kk][n] = (k < I_) ? wr[n * I_ + k] : 0.0f;
        }
        __syncthreads();

#pragma unroll 4
        for (int kk = 0; kk < KC; kk++) {
            float a[8], bb[10];
#pragma unroll
            for (int im = 0; im < 8; im++) a[im] = xs[kk][im * 16 + ty];
#pragma unroll
            for (int in = 0; in < 10; in++) bb[in] = ws[kk][in * 16 + tx];
#pragma unroll
            for (int im = 0; im < 8; im++)
#pragma unroll
                for (int in = 0; in < 10; in++)
                    acc[im][in] = fmaf(a[im], bb[in], acc[im][in]);
        }
        __syncthreads();
    }

    float* ur = g_uhat + (size_t)r * N_;
#pragma unroll
    for (int im = 0; im < 8; im++) {
        int m = im * 16 + ty;                  // batch index
#pragma unroll
        for (int in = 0; in < 10; in++)
            ur[(size_t)m * BRS + in * 16 + tx] = acc[im][in];
    }
}

// ---------------------------------------------------------------------------
// c[:,c] = softmax over routes (axis=0) of g_b. One block per capsule c.
__global__ void softmax_kernel() {
    const int c = blockIdx.x;
    const int t = threadIdx.x;
    __shared__ float red[256];

    float mx = -1e30f;
    for (int r = t; r < R_; r += 256) mx = fmaxf(mx, g_b[r * C_ + c]);
    red[t] = mx; __syncthreads();
    for (int s = 128; s; s >>= 1) {
        if (t < s) red[t] = fmaxf(red[t], red[t + s]);
        __syncthreads();
    }
    mx = red[0]; __syncthreads();

    float sum = 0.0f;
    for (int r = t; r < R_; r += 256) sum += expf(g_b[r * C_ + c] - mx);
    red[t] = sum; __syncthreads();
    for (int s = 128; s; s >>= 1) {
        if (t < s) red[t] += red[t + s];
        __syncthreads();
    }
    float inv = 1.0f / red[0];

    for (int r = t; r < R_; r += 256)
        g_c[r * C_ + c] = expf(g_b[r * C_ + c] - mx) * inv;
}

// ---------------------------------------------------------------------------
// s[b][n] = sum_r c[r][c(n)] * u_hat[b][r][n];  v = squash(s)
// One block per batch b, 640 threads = 4 r-slices x 160 n.
__global__ __launch_bounds__(640) void sv_kernel(int write_out, float* __restrict__ out) {
    const int b = blockIdx.x;
    const int t = threadIdx.x;
    const int q = t / 160;          // r-slice 0..3
    const int n = t - q * 160;
    const int c = n >> 4;
    const float* ub = g_uhat + (size_t)b * BRS;

    float acc = 0.0f;
#pragma unroll 4
    for (int r = q; r < R_; r += 4)
        acc += g_c[r * C_ + c] * ub[r * N_ + n];

    __shared__ float red[640];
    red[t] = acc;
    __syncthreads();
    if (t < 160) {
        float s = red[t] + red[t + 160] + red[t + 320] + red[t + 480];
        float v = s * fabsf(s) / (1.0f + s * s);     // squash
        g_v[b * N_ + t] = v;
        if (write_out) out[b * N_ + t] = v;
    }
}

// ---------------------------------------------------------------------------
// b[r][c] += (1/B) * sum_b sum_o u_hat[b][r][c][o] * v[b][c][o]
// One block per route r, 160 threads (one per n), shfl-reduce over o.
__global__ __launch_bounds__(160) void agree_kernel() {
    const int r = blockIdx.x;
    const int n = threadIdx.x;
    const int o = n & 15;
    const float* up = g_uhat + (size_t)r * N_ + n;

    float acc = 0.0f;
#pragma unroll 4
    for (int b = 0; b < B_; b++)
        acc += up[(size_t)b * BRS] * g_v[b * N_ + n];

#pragma unroll
    for (int off = 8; off; off >>= 1)
        acc += __shfl_down_sync(0xffffffffu, acc, off, 16);

    if (o == 0) g_b[r * C_ + (n >> 4)] += acc * (1.0f / 128.0f);
}

// ---------------------------------------------------------------------------
extern "C" void kernel_launch(void* const* d_in, const int* in_sizes, int n_in,
                              void* d_out, int out_size) {
    const float* x = (const float*)d_in[0];
    const float* W = (const float*)d_in[1];
    // defensive input-order detection: W has 62,300,160 elems, x 49,840,128
    if (n_in >= 2 && in_sizes[0] == R_ * C_ * O_ * I_) {
        W = (const float*)d_in[0];
        x = (const float*)d_in[1];
    }
    float* out = (float*)d_out;

    zero_b_kernel<<<(R_ * C_ + 255) / 256, 256>>>();
    uhat_kernel<<<R_, 256>>>(x, W);
    for (int it = 0; it < 3; it++) {
        softmax_kernel<<<C_, 256>>>();
        sv_kernel<<<B_, 640>>>(it == 2 ? 1 : 0, out);
        if (it < 2) agree_kernel<<<R_, 160>>>();
    }
}